// round 1
// baseline (speedup 1.0000x reference)
#include <cuda_runtime.h>
#include <math.h>

#define NH   64
#define NI   128
#define NHID 512
#define NO   256
#define NS   4

// Scratch (device globals — no allocation allowed)
__device__ float g_h1[NH * NHID];        // 128 KB
__device__ float g_psm[NS * NH * NO];    // 256 KB  softmax partials per (s,h)
__device__ float g_scalar[NH * NO];      // 64 KB   row-sums of ws

__device__ __forceinline__ float warp_sum(float v) {
#pragma unroll
    for (int o = 16; o; o >>= 1) v += __shfl_down_sync(0xffffffffu, v, o);
    return v;
}

template <int NW>
__device__ __forceinline__ float block_sum(float v, float* red, int tid) {
    v = warp_sum(v);
    if ((tid & 31) == 0) red[tid >> 5] = v;
    __syncthreads();
    if (tid < 32) {
        float x = (tid < NW) ? red[tid] : 0.f;
        x = warp_sum(x);
        if (tid == 0) red[0] = x;
    }
    __syncthreads();
    float r = red[0];
    __syncthreads();
    return r;
}

template <int NW>
__device__ __forceinline__ float block_max(float v, float* red, int tid) {
#pragma unroll
    for (int o = 16; o; o >>= 1) v = fmaxf(v, __shfl_down_sync(0xffffffffu, v, o));
    if ((tid & 31) == 0) red[tid >> 5] = v;
    __syncthreads();
    if (tid < 32) {
        float x = (tid < NW) ? red[tid] : -INFINITY;
#pragma unroll
        for (int o = 16; o; o >>= 1) x = fmaxf(x, __shfl_down_sync(0xffffffffu, x, o));
        if (tid == 0) red[0] = x;
    }
    __syncthreads();
    float r = red[0];
    __syncthreads();
    return r;
}

// ---------------------------------------------------------------------------
// Kernel 1: per-head  sub = x @ qw_h ;  z1 = w1_h @ sub ;  GN ; softplus
// grid = 64 (head), block = 512 (16 warps)
// ---------------------------------------------------------------------------
__global__ __launch_bounds__(512) void k_h1(
    const float* __restrict__ x, const float* __restrict__ qw,
    const float* __restrict__ w1, const float* __restrict__ g1,
    const float* __restrict__ b1)
{
    const int h = blockIdx.x;
    const int tid = threadIdx.x, warp = tid >> 5, lane = tid & 31;
    __shared__ float s_qw[NI];
    __shared__ float s_sub[NI];
    __shared__ float s_z[NHID];
    __shared__ float red[32];

    if (tid < NI) s_qw[tid] = qw[h * NI + tid];
    __syncthreads();

    // sub[r] = sum_c x[r,c] * qw[h,c]   (x is L2-resident, reused by all heads)
    for (int r = warp; r < NI; r += 16) {
        float4 xv = ((const float4*)(x + (size_t)r * NI))[lane];
        float acc = xv.x * s_qw[lane * 4 + 0] + xv.y * s_qw[lane * 4 + 1]
                  + xv.z * s_qw[lane * 4 + 2] + xv.w * s_qw[lane * 4 + 3];
        acc = warp_sum(acc);
        if (lane == 0) s_sub[r] = acc;
    }
    __syncthreads();

    // z1[o] = sum_i w1[h,o,i] * sub[i]   — warp-per-row, 4 rows unrolled (MLP=4)
    const float* w1h = w1 + (size_t)h * NHID * NI;
    for (int o = warp; o < NHID; o += 64) {
        float acc[4];
#pragma unroll
        for (int k = 0; k < 4; k++) {
            const int oo = o + k * 16;
            float4 a = ((const float4*)(w1h + (size_t)oo * NI))[lane];
            acc[k] = a.x * s_sub[lane * 4 + 0] + a.y * s_sub[lane * 4 + 1]
                   + a.z * s_sub[lane * 4 + 2] + a.w * s_sub[lane * 4 + 3];
        }
#pragma unroll
        for (int k = 0; k < 4; k++) {
            float v = warp_sum(acc[k]);
            if (lane == 0) s_z[o + k * 16] = v;
        }
    }
    __syncthreads();

    // GroupNorm over NHID, then softplus
    float v = s_z[tid];
    float sum = block_sum<16>(v, red, tid);
    float sq  = block_sum<16>(v * v, red, tid);
    float mean = sum * (1.f / NHID);
    float var  = sq * (1.f / NHID) - mean * mean;
    float zn = (v - mean) * rsqrtf(var + 1e-5f) * g1[h * NHID + tid] + b1[h * NHID + tid];
    float sp = fmaxf(zn, 0.f) + log1pf(expf(-fabsf(zn)));
    g_h1[h * NHID + tid] = sp;
}

// ---------------------------------------------------------------------------
// Kernel 2: scalar[h,o] = sum_j ws[h,o,j]  — warp per row, 16384 warps total
// grid = 2048, block = 256
// ---------------------------------------------------------------------------
__global__ __launch_bounds__(256) void k_ws(const float* __restrict__ ws)
{
    const int row  = (blockIdx.x << 3) + (threadIdx.x >> 5);  // 0..16383 = h*256+o
    const int lane = threadIdx.x & 31;
    const float4* r = (const float4*)(ws + (size_t)row * NO);
    float4 a = r[lane], b = r[lane + 32];
    float acc = a.x + a.y + a.z + a.w + b.x + b.y + b.z + b.w;
    acc = warp_sum(acc);
    if (lane == 0) g_scalar[row] = acc;
}

// ---------------------------------------------------------------------------
// Kernel 3 (the 128 MB stream): z = w2[s,h] @ h1[h] ; GN ; softmax -> g_psm
// grid = (64, 4) (h, s), block = 512 (16 warps), 2 rows x 4 float4 per iter
// ---------------------------------------------------------------------------
__global__ __launch_bounds__(512) void k_z2(
    const float* __restrict__ w2, const float* __restrict__ g2,
    const float* __restrict__ b2)
{
    const int h = blockIdx.x, s = blockIdx.y;
    const int tid = threadIdx.x, warp = tid >> 5, lane = tid & 31;
    __shared__ float s_h1[NHID];
    __shared__ float s_z[NO];
    __shared__ float red[32];

    s_h1[tid] = g_h1[h * NHID + tid];
    __syncthreads();

    const float* w2b = w2 + (size_t)(s * NH + h) * NO * NHID;
    for (int o = warp; o < NO; o += 32) {
        const float4* r0 = (const float4*)(w2b + (size_t)o * NHID);
        const float4* r1 = (const float4*)(w2b + (size_t)(o + 16) * NHID);
        float acc0 = 0.f, acc1 = 0.f;
#pragma unroll
        for (int c = 0; c < 4; c++) {
            const int i = lane + c * 32;
            float4 a = r0[i];
            float4 b = r1[i];
            float4 hv = ((const float4*)s_h1)[i];
            acc0 += a.x * hv.x + a.y * hv.y + a.z * hv.z + a.w * hv.w;
            acc1 += b.x * hv.x + b.y * hv.y + b.z * hv.z + b.w * hv.w;
        }
        acc0 = warp_sum(acc0);
        acc1 = warp_sum(acc1);
        if (lane == 0) { s_z[o] = acc0; s_z[o + 16] = acc1; }
    }
    __syncthreads();

    // GroupNorm over NO values (threads >= NO contribute identity elements)
    float v = (tid < NO) ? s_z[tid] : 0.f;
    float sum = block_sum<16>(v, red, tid);
    float sq  = block_sum<16>(v * v, red, tid);
    float mean = sum * (1.f / NO);
    float var  = sq * (1.f / NO) - mean * mean;
    const int gidx = (s * NH + h) * NO + tid;
    float zn = 0.f;
    if (tid < NO) zn = (v - mean) * rsqrtf(var + 1e-5f) * g2[gidx] + b2[gidx];

    // softmax over NO
    float m  = block_max<16>((tid < NO) ? zn : -INFINITY, red, tid);
    float e  = (tid < NO) ? expf(zn - m) : 0.f;
    float es = block_sum<16>(e, red, tid);
    if (tid < NO) g_psm[(s * NH + h) * NO + tid] = e / es;
}

// ---------------------------------------------------------------------------
// Kernel 4: combine partials, gate, scale, clip, write outputs
// grid = 64 (head), block = 256 (o)
// ---------------------------------------------------------------------------
__global__ __launch_bounds__(256) void k_final(
    const float* __restrict__ last, const float* __restrict__ woo,
    float* __restrict__ out)
{
    const int h = blockIdx.x;
    const int o = threadIdx.x;
    __shared__ float red[32];

    // last_prod[o] = prod_k last_out_sm[o,k]   (tiny, L2-resident)
    float lp = 1.f;
#pragma unroll
    for (int k = 0; k < NH; k++) lp *= last[o * NH + k];

    // out_sm[o,h] = sum_s softmax partials
    float osm = g_psm[(0 * NH + h) * NO + o] + g_psm[(1 * NH + h) * NO + o]
              + g_psm[(2 * NH + h) * NO + o] + g_psm[(3 * NH + h) * NO + o];

    // gate_logit[h] = woo[h,:256]·last_prod + woo[h,256:]·out_sm[:,h]
    float part = woo[h * 512 + o] * lp + woo[h * 512 + 256 + o] * osm;
    float gl = block_sum<8>(part, red, o);
    float onoff = 1.f / (1.f + expf(-gl));

    float oo = onoff * osm;
    float out0 = fmaxf(oo, 1e-14f);
    float sc = g_scalar[h * NO + o];
    float raw = oo * sc;
    float out1 = (fabsf(raw) <= 1e-14f) ? 1e-14f : raw;

    out[o * NH + h] = out0;                 // clipped on_off_out_sm (256,64)
    out[NO * NH + o * NH + h] = out1;       // out_scaled (256,64)
}

// ---------------------------------------------------------------------------
extern "C" void kernel_launch(void* const* d_in, const int* in_sizes, int n_in,
                              void* d_out, int out_size)
{
    const float* x    = (const float*)d_in[0];
    const float* last = (const float*)d_in[1];
    const float* qw   = (const float*)d_in[2];
    const float* w1   = (const float*)d_in[3];
    const float* g1   = (const float*)d_in[4];
    const float* b1   = (const float*)d_in[5];
    const float* w2   = (const float*)d_in[6];
    const float* g2   = (const float*)d_in[7];
    const float* b2   = (const float*)d_in[8];
    const float* ws   = (const float*)d_in[9];
    const float* woo  = (const float*)d_in[10];
    float* out = (float*)d_out;

    k_h1<<<NH, 512>>>(x, qw, w1, g1, b1);
    k_ws<<<2048, 256>>>(ws);
    dim3 gz(NH, NS);
    k_z2<<<gz, 512>>>(w2, g2, b2);
    k_final<<<NH, 256>>>(last, woo, out);
}

// round 2
// speedup vs baseline: 1.1923x; 1.1923x over previous
#include <cuda_runtime.h>
#include <math.h>

#define NH   64
#define NI   128
#define NHID 512
#define NO   256
#define NS   4

// Scratch (device globals — no allocation allowed)
__device__ float g_h1[NH * NHID];        // 128 KB
__device__ float g_psm[NS * NH * NO];    // 256 KB softmax partials per (s,h)
__device__ float g_scalar[NH * NO];      // 64 KB row-sums of ws
__device__ float g_lp[NO];               // 1 KB  last_prod

__device__ __forceinline__ float warp_sum(float v) {
#pragma unroll
    for (int o = 16; o; o >>= 1) v += __shfl_down_sync(0xffffffffu, v, o);
    return v;
}

template <int NW>
__device__ __forceinline__ float block_sum(float v, float* red, int tid) {
    v = warp_sum(v);
    if ((tid & 31) == 0) red[tid >> 5] = v;
    __syncthreads();
    if (tid < 32) {
        float x = (tid < NW) ? red[tid] : 0.f;
        x = warp_sum(x);
        if (tid == 0) red[0] = x;
    }
    __syncthreads();
    float r = red[0];
    __syncthreads();
    return r;
}

template <int NW>
__device__ __forceinline__ float block_max(float v, float* red, int tid) {
#pragma unroll
    for (int o = 16; o; o >>= 1) v = fmaxf(v, __shfl_down_sync(0xffffffffu, v, o));
    if ((tid & 31) == 0) red[tid >> 5] = v;
    __syncthreads();
    if (tid < 32) {
        float x = (tid < NW) ? red[tid] : -INFINITY;
#pragma unroll
        for (int o = 16; o; o >>= 1) x = fmaxf(x, __shfl_xor_sync(0xffffffffu, x, o));
        if (tid == 0) red[0] = x;
    }
    __syncthreads();
    float r = red[0];
    __syncthreads();
    return r;
}

// ---------------------------------------------------------------------------
// k_pre: merged kernel, block = 512
//   blocks [0,64)      : h1 path  (sub = x@qw ; z1 = w1@sub ; GN ; softplus)
//   blocks [64,80)     : last_prod (warp per output row, coalesced)
//   blocks [80,1104)   : ws row sums (warp per row)
// h1 blocks come first so they start in wave 1; ws blocks keep DRAM busy.
// ---------------------------------------------------------------------------
__global__ __launch_bounds__(512) void k_pre(
    const float* __restrict__ x, const float* __restrict__ qw,
    const float* __restrict__ w1, const float* __restrict__ g1,
    const float* __restrict__ b1, const float* __restrict__ ws,
    const float* __restrict__ last)
{
    const int bid = blockIdx.x;
    const int tid = threadIdx.x, warp = tid >> 5, lane = tid & 31;

    if (bid >= 80) {
        // ---- ws row sums: row = h*NO + o, 16384 rows of 256 floats ----
        const int row = (bid - 80) * 16 + warp;
        const float4* r = (const float4*)(ws + (size_t)row * NO);
        float4 a = r[lane], b = r[lane + 32];
        float acc = a.x + a.y + a.z + a.w + b.x + b.y + b.z + b.w;
        acc = warp_sum(acc);
        if (lane == 0) g_scalar[row] = acc;
        return;
    }

    if (bid >= 64) {
        // ---- last_prod: warp per output row o, product over 64 heads ----
        const int o = (bid - 64) * 16 + warp;
        float v = last[o * NH + lane] * last[o * NH + 32 + lane];
#pragma unroll
        for (int m = 16; m; m >>= 1) v *= __shfl_xor_sync(0xffffffffu, v, m);
        if (lane == 0) g_lp[o] = v;
        return;
    }

    // ---- h1 path, head h = bid ----
    const int h = bid;
    __shared__ float s_qw[NI];
    __shared__ float s_sub[NI];
    __shared__ float s_z[NHID];
    __shared__ float red[32];

    if (tid < NI) s_qw[tid] = qw[h * NI + tid];
    __syncthreads();

    for (int r = warp; r < NI; r += 16) {
        float4 xv = ((const float4*)(x + (size_t)r * NI))[lane];
        float acc = xv.x * s_qw[lane * 4 + 0] + xv.y * s_qw[lane * 4 + 1]
                  + xv.z * s_qw[lane * 4 + 2] + xv.w * s_qw[lane * 4 + 3];
        acc = warp_sum(acc);
        if (lane == 0) s_sub[r] = acc;
    }
    __syncthreads();

    const float* w1h = w1 + (size_t)h * NHID * NI;
    for (int o = warp; o < NHID; o += 64) {
        float acc[4];
#pragma unroll
        for (int k = 0; k < 4; k++) {
            const int oo = o + k * 16;
            float4 a = ((const float4*)(w1h + (size_t)oo * NI))[lane];
            acc[k] = a.x * s_sub[lane * 4 + 0] + a.y * s_sub[lane * 4 + 1]
                   + a.z * s_sub[lane * 4 + 2] + a.w * s_sub[lane * 4 + 3];
        }
#pragma unroll
        for (int k = 0; k < 4; k++) {
            float v = warp_sum(acc[k]);
            if (lane == 0) s_z[o + k * 16] = v;
        }
    }
    __syncthreads();

    float v = s_z[tid];
    float sum = block_sum<16>(v, red, tid);
    float sq  = block_sum<16>(v * v, red, tid);
    float mean = sum * (1.f / NHID);
    float var  = sq * (1.f / NHID) - mean * mean;
    float zn = (v - mean) * rsqrtf(var + 1e-5f) * g1[h * NHID + tid] + b1[h * NHID + tid];
    float sp = fmaxf(zn, 0.f) + log1pf(expf(-fabsf(zn)));
    g_h1[h * NHID + tid] = sp;
}

// ---------------------------------------------------------------------------
// k_z2 (the 128 MB stream): z = w2[s,h] @ h1[h] ; GN ; softmax -> g_psm
// grid = (64, 4), block = 512 (16 warps). Each warp owns 16 consecutive rows,
// accumulates all 16 in registers (4 rows x 4 float4 in flight), reduces once.
// ---------------------------------------------------------------------------
__global__ __launch_bounds__(512) void k_z2(
    const float* __restrict__ w2, const float* __restrict__ g2,
    const float* __restrict__ b2)
{
    const int h = blockIdx.x, s = blockIdx.y;
    const int tid = threadIdx.x, warp = tid >> 5, lane = tid & 31;
    __shared__ float s_h1[NHID];
    __shared__ float s_z[NO];
    __shared__ float red[32];

    s_h1[tid] = g_h1[h * NHID + tid];
    __syncthreads();

    const float* w2b = w2 + (size_t)(s * NH + h) * NO * NHID;
    const int base = warp * 16;
    const float4* hv4 = (const float4*)s_h1;

    float acc[16];
#pragma unroll 4
    for (int rr = 0; rr < 16; rr++) {
        const float4* row = (const float4*)(w2b + (size_t)(base + rr) * NHID);
        float a = 0.f;
#pragma unroll
        for (int c = 0; c < 4; c++) {
            float4 w  = row[lane + c * 32];
            float4 hv = hv4[lane + c * 32];
            a += w.x * hv.x + w.y * hv.y + w.z * hv.z + w.w * hv.w;
        }
        acc[rr] = a;
    }

    // 16 independent butterfly reductions (pipelined, no per-iter sync chain)
    float myv = 0.f;
#pragma unroll
    for (int rr = 0; rr < 16; rr++) {
        float v = acc[rr];
#pragma unroll
        for (int m = 16; m; m >>= 1) v += __shfl_xor_sync(0xffffffffu, v, m);
        if (lane == rr) myv = v;
    }
    if (lane < 16) s_z[base + lane] = myv;
    __syncthreads();

    // GroupNorm over NO values (threads >= NO contribute identity elements)
    float v = (tid < NO) ? s_z[tid] : 0.f;
    float sum = block_sum<16>(v, red, tid);
    float sq  = block_sum<16>(v * v, red, tid);
    float mean = sum * (1.f / NO);
    float var  = sq * (1.f / NO) - mean * mean;
    const int gidx = (s * NH + h) * NO + tid;
    float zn = 0.f;
    if (tid < NO) zn = (v - mean) * rsqrtf(var + 1e-5f) * g2[gidx] + b2[gidx];

    float m  = block_max<16>((tid < NO) ? zn : -INFINITY, red, tid);
    float e  = (tid < NO) ? expf(zn - m) : 0.f;
    float es = block_sum<16>(e, red, tid);
    if (tid < NO) g_psm[(s * NH + h) * NO + tid] = e / es;
}

// ---------------------------------------------------------------------------
// k_final: combine partials, gate, scale, clip, write outputs
// grid = 64 (head), block = 256 (o)
// ---------------------------------------------------------------------------
__global__ __launch_bounds__(256) void k_final(
    const float* __restrict__ woo, float* __restrict__ out)
{
    const int h = blockIdx.x;
    const int o = threadIdx.x;
    __shared__ float red[32];

    float lp = g_lp[o];

    float osm = g_psm[(0 * NH + h) * NO + o] + g_psm[(1 * NH + h) * NO + o]
              + g_psm[(2 * NH + h) * NO + o] + g_psm[(3 * NH + h) * NO + o];

    float part = woo[h * 512 + o] * lp + woo[h * 512 + 256 + o] * osm;
    float gl = block_sum<8>(part, red, o);
    float onoff = 1.f / (1.f + expf(-gl));

    float oo = onoff * osm;
    float out0 = fmaxf(oo, 1e-14f);
    float sc = g_scalar[h * NO + o];
    float raw = oo * sc;
    float out1 = (fabsf(raw) <= 1e-14f) ? 1e-14f : raw;

    out[o * NH + h] = out0;                 // clipped on_off_out_sm (256,64)
    out[NO * NH + o * NH + h] = out1;       // out_scaled (256,64)
}

// ---------------------------------------------------------------------------
extern "C" void kernel_launch(void* const* d_in, const int* in_sizes, int n_in,
                              void* d_out, int out_size)
{
    const float* x    = (const float*)d_in[0];
    const float* last = (const float*)d_in[1];
    const float* qw   = (const float*)d_in[2];
    const float* w1   = (const float*)d_in[3];
    const float* g1   = (const float*)d_in[4];
    const float* b1   = (const float*)d_in[5];
    const float* w2   = (const float*)d_in[6];
    const float* g2   = (const float*)d_in[7];
    const float* b2   = (const float*)d_in[8];
    const float* ws   = (const float*)d_in[9];
    const float* woo  = (const float*)d_in[10];
    float* out = (float*)d_out;

    k_pre<<<1104, 512>>>(x, qw, w1, g1, b1, ws, last);
    dim3 gz(NH, NS);
    k_z2<<<gz, 512>>>(w2, g2, b2);
    k_final<<<NH, 256>>>(woo, out);
}

// round 3
// speedup vs baseline: 1.2407x; 1.0406x over previous
#include <cuda_runtime.h>
#include <math.h>

#define NH   64
#define NI   128
#define NHID 512
#define NO   256
#define NS   4

#define B_H1 64
#define B_WS 128
#define B_W2 1024
#define NBLK (B_H1 + B_WS + B_W2 + NH)   // 1280
#define CNT_TARGET 18u                    // 16 w2 chunks + 2 ws blocks per head

// Scratch (device globals — zero-initialized at load)
__device__ float g_h1[NH * NHID];
__device__ float g_z[NS * NH * NO];
__device__ float g_scalar[NH * NO];
__device__ unsigned g_flag[NH];
__device__ unsigned g_cnt[NH];

__device__ __forceinline__ float warp_sum(float v) {
#pragma unroll
    for (int o = 16; o; o >>= 1) v += __shfl_xor_sync(0xffffffffu, v, o);
    return v;
}

__device__ __forceinline__ unsigned ld_acq(const unsigned* p) {
    unsigned v;
    asm volatile("ld.acquire.gpu.u32 %0, [%1];" : "=r"(v) : "l"(p) : "memory");
    return v;
}

template <int NW>
__device__ __forceinline__ float block_sum(float v, float* red, int tid) {
    v = warp_sum(v);
    if ((tid & 31) == 0) red[tid >> 5] = v;
    __syncthreads();
    if (tid < 32) {
        float x = (tid < NW) ? red[tid] : 0.f;
        x = warp_sum(x);
        if (tid == 0) red[0] = x;
    }
    __syncthreads();
    float r = red[0];
    __syncthreads();
    return r;
}

// ---------------------------------------------------------------------------
// One fused kernel. Block roles by blockIdx.x (producers at low bids so all
// waiters' producers are guaranteed resident first — no deadlock).
// ---------------------------------------------------------------------------
__global__ void __launch_bounds__(512, 3) k_main(
    const float* __restrict__ x,   const float* __restrict__ qw,
    const float* __restrict__ w1,  const float* __restrict__ g1,
    const float* __restrict__ b1,  const float* __restrict__ w2,
    const float* __restrict__ g2,  const float* __restrict__ b2,
    const float* __restrict__ ws,  const float* __restrict__ last,
    const float* __restrict__ woo, float* __restrict__ out)
{
    const int bid = blockIdx.x;
    const int tid = threadIdx.x, warp = tid >> 5, lane = tid & 31;

    // ======================= h1 blocks: bids [0,64) ========================
    if (bid < B_H1) {
        const int h = bid;
        __shared__ float s_qw[NI];
        __shared__ float s_sub[NI];
        __shared__ float s_zh[NHID];
        __shared__ float red[32];

        if (tid < NI) s_qw[tid] = qw[h * NI + tid];
        __syncthreads();

        for (int r = warp; r < NI; r += 16) {
            float4 xv = ((const float4*)(x + (size_t)r * NI))[lane];
            float acc = xv.x * s_qw[lane * 4 + 0] + xv.y * s_qw[lane * 4 + 1]
                      + xv.z * s_qw[lane * 4 + 2] + xv.w * s_qw[lane * 4 + 3];
            acc = warp_sum(acc);
            if (lane == 0) s_sub[r] = acc;
        }
        __syncthreads();

        const float* w1h = w1 + (size_t)h * NHID * NI;
        for (int o = warp; o < NHID; o += 64) {
            float acc[4];
#pragma unroll
            for (int k = 0; k < 4; k++) {
                const int oo = o + k * 16;
                float4 a = ((const float4*)(w1h + (size_t)oo * NI))[lane];
                acc[k] = a.x * s_sub[lane * 4 + 0] + a.y * s_sub[lane * 4 + 1]
                       + a.z * s_sub[lane * 4 + 2] + a.w * s_sub[lane * 4 + 3];
            }
#pragma unroll
            for (int k = 0; k < 4; k++) {
                float v = warp_sum(acc[k]);
                if (lane == 0) s_zh[o + k * 16] = v;
            }
        }
        __syncthreads();

        float v = s_zh[tid];
        float sum = block_sum<16>(v, red, tid);
        float sq  = block_sum<16>(v * v, red, tid);
        float mean = sum * (1.f / NHID);
        float var  = sq * (1.f / NHID) - mean * mean;
        float zn = (v - mean) * rsqrtf(var + 1e-5f) * g1[h * NHID + tid] + b1[h * NHID + tid];
        float sp = fmaxf(zn, 0.f) + log1pf(expf(-fabsf(zn)));
        g_h1[h * NHID + tid] = sp;
        __syncthreads();
        if (tid == 0) { __threadfence(); atomicExch(&g_flag[h], 1u); }
        return;
    }

    // ======================= ws blocks: bids [64,192) ======================
    if (bid < B_H1 + B_WS) {
        const int wsb = bid - B_H1;                 // 0..127
        const int rowbase = wsb * 128 + warp * 8;   // 8 rows per warp
        float acc[8];
#pragma unroll
        for (int rr = 0; rr < 8; rr++) {
            const float4* r = (const float4*)(ws + (size_t)(rowbase + rr) * NO);
            float4 a = r[lane], b = r[lane + 32];
            acc[rr] = a.x + a.y + a.z + a.w + b.x + b.y + b.z + b.w;
        }
        float myv = 0.f;
#pragma unroll
        for (int rr = 0; rr < 8; rr++) {
            float v = acc[rr];
#pragma unroll
            for (int m = 16; m; m >>= 1) v += __shfl_xor_sync(0xffffffffu, v, m);
            if (lane == rr) myv = v;
        }
        if (lane < 8) g_scalar[rowbase + lane] = myv;
        __syncthreads();
        if (tid == 0) { __threadfence(); atomicAdd(&g_cnt[wsb >> 1], 1u); }
        return;
    }

    // ======================= w2 blocks: bids [192,1216) ====================
    if (bid < B_H1 + B_WS + B_W2) {
        const int b2i = bid - (B_H1 + B_WS);
        const int chunk = b2i & 3, sh = b2i >> 2;
        const int h = sh & 63, s = sh >> 6;
        __shared__ float s_h1s[NHID];

        if (tid == 0) { while (ld_acq(&g_flag[h]) == 0u) __nanosleep(64); }
        __syncthreads();
        s_h1s[tid] = g_h1[h * NHID + tid];
        __syncthreads();

        const float* wb = w2 + ((size_t)(s * NH + h) * NO + chunk * 64) * NHID;
        const int r0 = warp * 4;
        const float4* hv4 = (const float4*)s_h1s;
        float acc[4];
#pragma unroll
        for (int rr = 0; rr < 4; rr++) {
            const float4* row = (const float4*)(wb + (size_t)(r0 + rr) * NHID);
            float a = 0.f;
#pragma unroll
            for (int c = 0; c < 4; c++) {
                float4 w_ = row[lane + c * 32];
                float4 hv = hv4[lane + c * 32];
                a += w_.x * hv.x + w_.y * hv.y + w_.z * hv.z + w_.w * hv.w;
            }
            acc[rr] = a;
        }
        float myv = 0.f;
#pragma unroll
        for (int rr = 0; rr < 4; rr++) {
            float v = acc[rr];
#pragma unroll
            for (int m = 16; m; m >>= 1) v += __shfl_xor_sync(0xffffffffu, v, m);
            if (lane == rr) myv = v;
        }
        if (lane < 4)
            g_z[(size_t)(s * NH + h) * NO + chunk * 64 + r0 + lane] = myv;
        __syncthreads();
        if (tid == 0) { __threadfence(); atomicAdd(&g_cnt[h], 1u); }
        return;
    }

    // ===================== epilogue blocks: bids [1216,1280) ===============
    {
        const int h = bid - (B_H1 + B_WS + B_W2);
        __shared__ float s_z[NS * NO];    // z, then psm in place
        __shared__ float s_lp[NO];
        __shared__ float rsum[16], rsq[16], rmax[16], resum[16], redg[16];

        // last_prod (coalesced, overlaps the wait below)
#pragma unroll
        for (int k = 0; k < 16; k++) {
            const int o = k * 16 + warp;
            float v = last[o * NH + lane] * last[o * NH + 32 + lane];
#pragma unroll
            for (int m = 16; m; m >>= 1) v *= __shfl_xor_sync(0xffffffffu, v, m);
            if (lane == 0) s_lp[o] = v;
        }

        if (tid == 0) { while (ld_acq(&g_cnt[h]) != CNT_TARGET) __nanosleep(128); }
        __syncthreads();

        for (int i = tid; i < NS * NO; i += 512) {
            const int s = i >> 8, o = i & 255;
            s_z[i] = g_z[(size_t)(s * NH + h) * NO + o];
        }
        __syncthreads();

        // 4 GroupNorm+softmax, two per pass (two 256-thread groups in parallel)
#pragma unroll
        for (int pass = 0; pass < 2; pass++) {
            const int grp = tid >> 8;          // 0 or 1
            const int s = pass * 2 + grp;
            const int o = tid & 255;
            const int wg = (tid >> 5) & 7;

            float v = s_z[s * NO + o];
            float su = warp_sum(v);
            float sq = warp_sum(v * v);
            if (lane == 0) { rsum[grp * 8 + wg] = su; rsq[grp * 8 + wg] = sq; }
            __syncthreads();
            float sum = 0.f, sqs = 0.f;
#pragma unroll
            for (int j = 0; j < 8; j++) { sum += rsum[grp * 8 + j]; sqs += rsq[grp * 8 + j]; }
            float mean = sum * (1.f / NO);
            float var  = sqs * (1.f / NO) - mean * mean;
            const int gidx = (s * NH + h) * NO + o;
            float zn = (v - mean) * rsqrtf(var + 1e-5f) * g2[gidx] + b2[gidx];

            float mx = zn;
#pragma unroll
            for (int m = 16; m; m >>= 1) mx = fmaxf(mx, __shfl_xor_sync(0xffffffffu, mx, m));
            if (lane == 0) rmax[grp * 8 + wg] = mx;
            __syncthreads();
            float M = -INFINITY;
#pragma unroll
            for (int j = 0; j < 8; j++) M = fmaxf(M, rmax[grp * 8 + j]);

            float e = expf(zn - M);
            float se = warp_sum(e);
            if (lane == 0) resum[grp * 8 + wg] = se;
            __syncthreads();
            float es = 0.f;
#pragma unroll
            for (int j = 0; j < 8; j++) es += resum[grp * 8 + j];
            s_z[s * NO + o] = e / es;
            __syncthreads();
        }

        // combine: osm, gate, outputs
        const int o = tid;
        float osm = 0.f, part = 0.f;
        if (tid < NO) {
            osm = s_z[o] + s_z[NO + o] + s_z[2 * NO + o] + s_z[3 * NO + o];
            part = woo[h * 2 * NO + o] * s_lp[o] + woo[h * 2 * NO + NO + o] * osm;
        }
        float ps = warp_sum(part);
        if (lane == 0) redg[warp] = ps;
        __syncthreads();
        float gl = 0.f;
#pragma unroll
        for (int j = 0; j < 16; j++) gl += redg[j];
        float onoff = 1.f / (1.f + expf(-gl));

        if (tid < NO) {
            float oo = onoff * osm;
            float out0 = fmaxf(oo, 1e-14f);
            float sc = g_scalar[h * NO + o];
            float raw = oo * sc;
            float out1 = (fabsf(raw) <= 1e-14f) ? 1e-14f : raw;
            out[o * NH + h] = out0;                 // clipped on_off_out_sm (256,64)
            out[NO * NH + o * NH + h] = out1;       // out_scaled (256,64)
        }
        __syncthreads();
        if (tid == 0) { g_cnt[h] = 0u; g_flag[h] = 0u; }  // reset for next replay
    }
}

// ---------------------------------------------------------------------------
extern "C" void kernel_launch(void* const* d_in, const int* in_sizes, int n_in,
                              void* d_out, int out_size)
{
    const float* x    = (const float*)d_in[0];
    const float* last = (const float*)d_in[1];
    const float* qw   = (const float*)d_in[2];
    const float* w1   = (const float*)d_in[3];
    const float* g1   = (const float*)d_in[4];
    const float* b1   = (const float*)d_in[5];
    const float* w2   = (const float*)d_in[6];
    const float* g2   = (const float*)d_in[7];
    const float* b2   = (const float*)d_in[8];
    const float* ws   = (const float*)d_in[9];
    const float* woo  = (const float*)d_in[10];
    float* out = (float*)d_out;

    k_main<<<NBLK, 512>>>(x, qw, w1, g1, b1, w2, g2, b2, ws, last, woo, out);
}

// round 4
// speedup vs baseline: 1.4882x; 1.1995x over previous
#include <cuda_runtime.h>
#include <math.h>

#define NH   64
#define NI   128
#define NHID 512
#define NO   256
#define NS   4

// Block-role layout
#define B_B    256                   // w1 streamers (4 per head)
#define B_WS   128                   // ws row-sums
#define B_C    64                    // GN+softplus per head
#define B_W2   512                   // w2 streamers (8 per head: 2 chunks x 4 s)
#define B_EPI  64
#define OFF_WS (B_B)                 // 256
#define OFF_C  (B_B + B_WS)          // 384
#define OFF_W2 (OFF_C + B_C)         // 448
#define OFF_EPI (OFF_W2 + B_W2)      // 960
#define NBLK   (OFF_EPI + B_EPI)     // 1024

#define CNTB_TARGET 4u               // 4 w1 quarters per head
#define CNT_TARGET  10u              // 8 w2 chunks + 2 ws blocks per head

// Scratch (device globals)
__device__ float g_z1[NH * NHID];
__device__ float g_h1[NH * NHID];
__device__ float g_z[NS * NH * NO];
__device__ float g_scalar[NH * NO];
__device__ unsigned g_cntb[NH];
__device__ unsigned g_cnt[NH];
__device__ unsigned g_flag[NH];

__device__ __forceinline__ float dot4(float4 a, float4 b) {
    return a.x * b.x + a.y * b.y + a.z * b.z + a.w * b.w;
}

__device__ __forceinline__ float warp_sum(float v) {
#pragma unroll
    for (int o = 16; o; o >>= 1) v += __shfl_xor_sync(0xffffffffu, v, o);
    return v;
}

__device__ __forceinline__ unsigned ld_acq(const unsigned* p) {
    unsigned v;
    asm volatile("ld.acquire.gpu.u32 %0, [%1];" : "=r"(v) : "l"(p) : "memory");
    return v;
}

template <int NW>
__device__ __forceinline__ float block_sum(float v, float* red, int tid) {
    v = warp_sum(v);
    if ((tid & 31) == 0) red[tid >> 5] = v;
    __syncthreads();
    if (tid < 32) {
        float x = (tid < NW) ? red[tid] : 0.f;
        x = warp_sum(x);
        if (tid == 0) red[0] = x;
    }
    __syncthreads();
    float r = red[0];
    __syncthreads();
    return r;
}

// ---------------------------------------------------------------------------
__global__ void __launch_bounds__(512, 2) k_main(
    const float* __restrict__ x,   const float* __restrict__ qw,
    const float* __restrict__ w1,  const float* __restrict__ g1,
    const float* __restrict__ b1,  const float* __restrict__ w2,
    const float* __restrict__ g2,  const float* __restrict__ b2,
    const float* __restrict__ ws,  const float* __restrict__ last,
    const float* __restrict__ woo, float* __restrict__ out)
{
    const int bid = blockIdx.x;
    const int tid = threadIdx.x, warp = tid >> 5, lane = tid & 31;

    // ============ B blocks [0,256): sub (redundant x4) + w1 quarter ========
    if (bid < B_B) {
        const int h = bid >> 2, q = bid & 3;
        __shared__ float s_qw[NI];
        __shared__ float s_sub[NI];

        if (tid < NI) s_qw[tid] = qw[h * NI + tid];
        __syncthreads();

        // sub[r] = x[r,:] . qw[h]   — 8 rows per warp, x is L2-hot
        {
            const float4* qv4 = (const float4*)s_qw;
            float4 qv = qv4[lane];
            float part[8];
#pragma unroll
            for (int rr = 0; rr < 8; rr++) {
                const int r = warp * 8 + rr;
                float4 xv = ((const float4*)(x + (size_t)r * NI))[lane];
                part[rr] = dot4(xv, qv);
            }
#pragma unroll
            for (int rr = 0; rr < 8; rr++) {
                float v = warp_sum(part[rr]);
                if (lane == rr) s_sub[warp * 8 + rr] = v;
            }
        }
        __syncthreads();

        // w1 quarter: 128 rows of 128, 8 rows per warp, deferred reductions
        {
            const int row0 = q * 128 + warp * 8;
            const float* w1b = w1 + ((size_t)h * NHID + row0) * NI;
            float4 sv = ((const float4*)s_sub)[lane];
            float acc[8];
#pragma unroll
            for (int rr = 0; rr < 8; rr++) {
                float4 wv = ((const float4*)(w1b + (size_t)rr * NI))[lane];
                acc[rr] = dot4(wv, sv);
            }
            float myv = 0.f;
#pragma unroll
            for (int rr = 0; rr < 8; rr++) {
                float v = warp_sum(acc[rr]);
                if (lane == rr) myv = v;
            }
            if (lane < 8) g_z1[(size_t)h * NHID + row0 + lane] = myv;
        }
        __syncthreads();
        if (tid == 0) { __threadfence(); atomicAdd(&g_cntb[h], 1u); }
        return;
    }

    // ============ ws blocks [256,384): row sums, 8 rows/warp ===============
    if (bid < OFF_C) {
        const int wsb = bid - OFF_WS;
        const int rowbase = wsb * 128 + warp * 8;
        float acc[8];
#pragma unroll
        for (int rr = 0; rr < 8; rr++) {
            const float4* r = (const float4*)(ws + (size_t)(rowbase + rr) * NO);
            float4 a = r[lane], b = r[lane + 32];
            acc[rr] = a.x + a.y + a.z + a.w + b.x + b.y + b.z + b.w;
        }
        float myv = 0.f;
#pragma unroll
        for (int rr = 0; rr < 8; rr++) {
            float v = warp_sum(acc[rr]);
            if (lane == rr) myv = v;
        }
        if (lane < 8) g_scalar[rowbase + lane] = myv;
        __syncthreads();
        if (tid == 0) { __threadfence(); atomicAdd(&g_cnt[wsb >> 1], 1u); }
        return;
    }

    // ============ C blocks [384,448): GN + softplus per head ===============
    if (bid < OFF_W2) {
        const int h = bid - OFF_C;
        __shared__ float red[32];
        if (tid == 0) { while (ld_acq(&g_cntb[h]) != CNTB_TARGET) __nanosleep(64); }
        __syncthreads();

        float v = g_z1[(size_t)h * NHID + tid];
        float sum = block_sum<16>(v, red, tid);
        float sq  = block_sum<16>(v * v, red, tid);
        float mean = sum * (1.f / NHID);
        float var  = sq * (1.f / NHID) - mean * mean;
        float zn = (v - mean) * rsqrtf(var + 1e-5f) * g1[h * NHID + tid] + b1[h * NHID + tid];
        float sp = fmaxf(zn, 0.f) + log1pf(expf(-fabsf(zn)));
        g_h1[(size_t)h * NHID + tid] = sp;
        __syncthreads();
        if (tid == 0) { __threadfence(); atomicExch(&g_flag[h], 1u); }
        return;
    }

    // ============ w2 blocks [448,960): 128-row chunk of (s,h) ==============
    if (bid < OFF_EPI) {
        const int b2i = bid - OFF_W2;           // 0..511
        const int chunk = b2i & 1, sh = b2i >> 1;
        const int h = sh & 63, s = sh >> 6;
        __shared__ float s_h1s[NHID];

        if (tid == 0) { while (ld_acq(&g_flag[h]) == 0u) __nanosleep(64); }
        __syncthreads();
        s_h1s[tid] = g_h1[(size_t)h * NHID + tid];
        __syncthreads();

        const int row0 = chunk * 128 + warp * 8;
        const float* wb = w2 + ((size_t)((s * NH + h) * NO) + row0) * NHID;
        const float4* hv4 = (const float4*)s_h1s;

        float acc[8] = {0.f, 0.f, 0.f, 0.f, 0.f, 0.f, 0.f, 0.f};
#pragma unroll
        for (int c = 0; c < 4; c++) {
            float4 hv = hv4[lane + c * 32];
#pragma unroll
            for (int rr = 0; rr < 8; rr++) {
                float4 wv = ((const float4*)(wb + (size_t)rr * NHID))[lane + c * 32];
                acc[rr] += dot4(wv, hv);
            }
        }
        float myv = 0.f;
#pragma unroll
        for (int rr = 0; rr < 8; rr++) {
            float v = warp_sum(acc[rr]);
            if (lane == rr) myv = v;
        }
        if (lane < 8)
            g_z[(size_t)(s * NH + h) * NO + row0 + lane] = myv;
        __syncthreads();
        if (tid == 0) { __threadfence(); atomicAdd(&g_cnt[h], 1u); }
        return;
    }

    // ============ epilogue blocks [960,1024) ===============================
    {
        const int h = bid - OFF_EPI;
        __shared__ float s_z[NS * NO];
        __shared__ float s_lp[NO];
        __shared__ float rsum[16], rsq[16], rmax[16], resum[16], redg[16];

        // last_prod (coalesced; overlaps the wait)
#pragma unroll
        for (int k = 0; k < 16; k++) {
            const int o = k * 16 + warp;
            float v = last[o * NH + lane] * last[o * NH + 32 + lane];
#pragma unroll
            for (int m = 16; m; m >>= 1) v *= __shfl_xor_sync(0xffffffffu, v, m);
            if (lane == 0) s_lp[o] = v;
        }

        if (tid == 0) { while (ld_acq(&g_cnt[h]) != CNT_TARGET) __nanosleep(128); }
        __syncthreads();

        for (int i = tid; i < NS * NO; i += 512) {
            const int s = i >> 8, o = i & 255;
            s_z[i] = g_z[(size_t)(s * NH + h) * NO + o];
        }
        __syncthreads();

        // 4 GroupNorm+softmax, two 256-thread groups per pass
#pragma unroll
        for (int pass = 0; pass < 2; pass++) {
            const int grp = tid >> 8;
            const int s = pass * 2 + grp;
            const int o = tid & 255;
            const int wg = (tid >> 5) & 7;

            float v = s_z[s * NO + o];
            float su = warp_sum(v);
            float sq = warp_sum(v * v);
            if (lane == 0) { rsum[grp * 8 + wg] = su; rsq[grp * 8 + wg] = sq; }
            __syncthreads();
            float sum = 0.f, sqs = 0.f;
#pragma unroll
            for (int j = 0; j < 8; j++) { sum += rsum[grp * 8 + j]; sqs += rsq[grp * 8 + j]; }
            float mean = sum * (1.f / NO);
            float var  = sqs * (1.f / NO) - mean * mean;
            const int gidx = (s * NH + h) * NO + o;
            float zn = (v - mean) * rsqrtf(var + 1e-5f) * g2[gidx] + b2[gidx];

            float mx = zn;
#pragma unroll
            for (int m = 16; m; m >>= 1) mx = fmaxf(mx, __shfl_xor_sync(0xffffffffu, mx, m));
            if (lane == 0) rmax[grp * 8 + wg] = mx;
            __syncthreads();
            float M = -INFINITY;
#pragma unroll
            for (int j = 0; j < 8; j++) M = fmaxf(M, rmax[grp * 8 + j]);

            float e = expf(zn - M);
            float se = warp_sum(e);
            if (lane == 0) resum[grp * 8 + wg] = se;
            __syncthreads();
            float es = 0.f;
#pragma unroll
            for (int j = 0; j < 8; j++) es += resum[grp * 8 + j];
            s_z[s * NO + o] = e / es;
            __syncthreads();
        }

        const int o = tid;
        float osm = 0.f, part = 0.f;
        if (tid < NO) {
            osm = s_z[o] + s_z[NO + o] + s_z[2 * NO + o] + s_z[3 * NO + o];
            part = woo[h * 2 * NO + o] * s_lp[o] + woo[h * 2 * NO + NO + o] * osm;
        }
        float ps = warp_sum(part);
        if (lane == 0) redg[warp] = ps;
        __syncthreads();
        float gl = 0.f;
#pragma unroll
        for (int j = 0; j < 16; j++) gl += redg[j];
        float onoff = 1.f / (1.f + expf(-gl));

        if (tid < NO) {
            float oo = onoff * osm;
            float out0 = fmaxf(oo, 1e-14f);
            float sc = g_scalar[h * NO + o];
            float raw = oo * sc;
            float out1 = (fabsf(raw) <= 1e-14f) ? 1e-14f : raw;
            out[o * NH + h] = out0;
            out[NO * NH + o * NH + h] = out1;
        }
        __syncthreads();
        if (tid == 0) { g_cnt[h] = 0u; g_cntb[h] = 0u; g_flag[h] = 0u; }
    }
}

// ---------------------------------------------------------------------------
extern "C" void kernel_launch(void* const* d_in, const int* in_sizes, int n_in,
                              void* d_out, int out_size)
{
    const float* x    = (const float*)d_in[0];
    const float* last = (const float*)d_in[1];
    const float* qw   = (const float*)d_in[2];
    const float* w1   = (const float*)d_in[3];
    const float* g1   = (const float*)d_in[4];
    const float* b1   = (const float*)d_in[5];
    const float* w2   = (const float*)d_in[6];
    const float* g2   = (const float*)d_in[7];
    const float* b2   = (const float*)d_in[8];
    const float* ws   = (const float*)d_in[9];
    const float* woo  = (const float*)d_in[10];
    float* out = (float*)d_out;

    k_main<<<NBLK, 512>>>(x, qw, w1, g1, b1, w2, g2, b2, ws, last, woo, out);
}

// round 5
// speedup vs baseline: 1.5090x; 1.0140x over previous
#include <cuda_runtime.h>
#include <math.h>

#define NH   64
#define NI   128
#define NHID 512
#define NO   256
#define NS   4

// Block-role layout
#define B_B    256                   // w1 streamers (4 per head)
#define B_WS   128                   // ws row-sums
#define B_W2   512                   // w2 streamers (8 per head: 2 chunks x 4 s)
#define B_EPI  64
#define OFF_WS (B_B)                 // 256
#define OFF_W2 (B_B + B_WS)          // 384
#define OFF_EPI (OFF_W2 + B_W2)      // 896
#define NBLK   (OFF_EPI + B_EPI)     // 960

#define CNTB_TARGET 4u               // 4 w1 quarters per head
#define CNT_TARGET  10u              // 8 w2 chunks + 2 ws blocks per head

// Scratch (device globals)
__device__ float g_z1[NH * NHID];
__device__ float g_z[NS * NH * NO];
__device__ float g_scalar[NH * NO];
__device__ unsigned g_cntb[NH];
__device__ unsigned g_cnt[NH];

__device__ __forceinline__ float dot4(float4 a, float4 b) {
    return a.x * b.x + a.y * b.y + a.z * b.z + a.w * b.w;
}

__device__ __forceinline__ float warp_sum(float v) {
#pragma unroll
    for (int o = 16; o; o >>= 1) v += __shfl_xor_sync(0xffffffffu, v, o);
    return v;
}

__device__ __forceinline__ unsigned ld_acq(const unsigned* p) {
    unsigned v;
    asm volatile("ld.acquire.gpu.u32 %0, [%1];" : "=r"(v) : "l"(p) : "memory");
    return v;
}

template <int NW>
__device__ __forceinline__ float block_sum(float v, float* red, int tid) {
    v = warp_sum(v);
    if ((tid & 31) == 0) red[tid >> 5] = v;
    __syncthreads();
    if (tid < 32) {
        float x = (tid < NW) ? red[tid] : 0.f;
        x = warp_sum(x);
        if (tid == 0) red[0] = x;
    }
    __syncthreads();
    float r = red[0];
    __syncthreads();
    return r;
}

// ---------------------------------------------------------------------------
__global__ void __launch_bounds__(512, 2) k_main(
    const float* __restrict__ x,   const float* __restrict__ qw,
    const float* __restrict__ w1,  const float* __restrict__ g1,
    const float* __restrict__ b1,  const float* __restrict__ w2,
    const float* __restrict__ g2,  const float* __restrict__ b2,
    const float* __restrict__ ws,  const float* __restrict__ last,
    const float* __restrict__ woo, float* __restrict__ out)
{
    const int bid = blockIdx.x;
    const int tid = threadIdx.x, warp = tid >> 5, lane = tid & 31;

    // ============ B blocks [0,256): sub (redundant x4) + w1 quarter ========
    if (bid < B_B) {
        const int h = bid >> 2, q = bid & 3;
        __shared__ float s_qw[NI];
        __shared__ float s_sub[NI];

        if (tid < NI) s_qw[tid] = qw[h * NI + tid];
        __syncthreads();

        // sub[r] = x[r,:] . qw[h]   — 8 rows per warp, x is L2-hot
        {
            float4 qv = ((const float4*)s_qw)[lane];
            float part[8];
#pragma unroll
            for (int rr = 0; rr < 8; rr++) {
                const int r = warp * 8 + rr;
                float4 xv = ((const float4*)(x + (size_t)r * NI))[lane];
                part[rr] = dot4(xv, qv);
            }
#pragma unroll
            for (int rr = 0; rr < 8; rr++) {
                float v = warp_sum(part[rr]);
                if (lane == rr) s_sub[warp * 8 + rr] = v;
            }
        }
        __syncthreads();

        // w1 quarter: 128 rows of 128, 8 rows per warp
        {
            const int row0 = q * 128 + warp * 8;
            const float* w1b = w1 + ((size_t)h * NHID + row0) * NI;
            float4 sv = ((const float4*)s_sub)[lane];
            float acc[8];
#pragma unroll
            for (int rr = 0; rr < 8; rr++) {
                float4 wv = ((const float4*)(w1b + (size_t)rr * NI))[lane];
                acc[rr] = dot4(wv, sv);
            }
            float myv = 0.f;
#pragma unroll
            for (int rr = 0; rr < 8; rr++) {
                float v = warp_sum(acc[rr]);
                if (lane == rr) myv = v;
            }
            if (lane < 8) g_z1[(size_t)h * NHID + row0 + lane] = myv;
        }
        __syncthreads();
        if (tid == 0) { __threadfence(); atomicAdd(&g_cntb[h], 1u); }
        return;
    }

    // ============ ws blocks [256,384): row sums, 8 rows/warp ===============
    if (bid < OFF_W2) {
        const int wsb = bid - OFF_WS;
        const int rowbase = wsb * 128 + warp * 8;
        float acc[8];
#pragma unroll
        for (int rr = 0; rr < 8; rr++) {
            const float4* r = (const float4*)(ws + (size_t)(rowbase + rr) * NO);
            float4 a = r[lane], b = r[lane + 32];
            acc[rr] = a.x + a.y + a.z + a.w + b.x + b.y + b.z + b.w;
        }
        float myv = 0.f;
#pragma unroll
        for (int rr = 0; rr < 8; rr++) {
            float v = warp_sum(acc[rr]);
            if (lane == rr) myv = v;
        }
        if (lane < 8) g_scalar[rowbase + lane] = myv;
        __syncthreads();
        if (tid == 0) { __threadfence(); atomicAdd(&g_cnt[wsb >> 1], 1u); }
        return;
    }

    // ===== w2 blocks [384,896): inline GN+softplus, then 128-row chunk =====
    if (bid < OFF_EPI) {
        const int b2i = bid - OFF_W2;           // 0..511
        const int chunk = b2i & 1, sh = b2i >> 1;
        const int h = sh & 63, s = sh >> 6;
        __shared__ float s_h1s[NHID];
        __shared__ float red[32];

        // wait directly on the w1 quarter counter (no C-block hop)
        if (tid == 0) { while (ld_acq(&g_cntb[h]) != CNTB_TARGET) __nanosleep(32); }
        __syncthreads();

        // inline GroupNorm + softplus for this head (redundant per block; L2-hot)
        {
            float v = g_z1[(size_t)h * NHID + tid];
            float sum = block_sum<16>(v, red, tid);
            float sq  = block_sum<16>(v * v, red, tid);
            float mean = sum * (1.f / NHID);
            float var  = sq * (1.f / NHID) - mean * mean;
            float zn = (v - mean) * rsqrtf(var + 1e-5f) * g1[h * NHID + tid]
                     + b1[h * NHID + tid];
            s_h1s[tid] = fmaxf(zn, 0.f) + log1pf(expf(-fabsf(zn)));
        }
        __syncthreads();

        const int row0 = chunk * 128 + warp * 8;
        const float* wb = w2 + ((size_t)((s * NH + h) * NO) + row0) * NHID;
        const float4* hv4 = (const float4*)s_h1s;

        float acc[8] = {0.f, 0.f, 0.f, 0.f, 0.f, 0.f, 0.f, 0.f};
#pragma unroll
        for (int c = 0; c < 4; c++) {
            float4 hv = hv4[lane + c * 32];
#pragma unroll
            for (int rr = 0; rr < 8; rr++) {
                float4 wv = ((const float4*)(wb + (size_t)rr * NHID))[lane + c * 32];
                acc[rr] += dot4(wv, hv);
            }
        }
        float myv = 0.f;
#pragma unroll
        for (int rr = 0; rr < 8; rr++) {
            float v = warp_sum(acc[rr]);
            if (lane == rr) myv = v;
        }
        if (lane < 8)
            g_z[(size_t)(s * NH + h) * NO + row0 + lane] = myv;
        __syncthreads();
        if (tid == 0) { __threadfence(); atomicAdd(&g_cnt[h], 1u); }
        return;
    }

    // ============ epilogue blocks [896,960) ================================
    {
        const int h = bid - OFF_EPI;
        __shared__ float s_z[NS * NO];
        __shared__ float s_lp[NO];
        __shared__ float rsum[16], rsq[16], rmax[16], resum[16], redg[16];

        // last_prod (coalesced; overlaps the wait)
#pragma unroll
        for (int k = 0; k < 16; k++) {
            const int o = k * 16 + warp;
            float v = last[o * NH + lane] * last[o * NH + 32 + lane];
#pragma unroll
            for (int m = 16; m; m >>= 1) v *= __shfl_xor_sync(0xffffffffu, v, m);
            if (lane == 0) s_lp[o] = v;
        }

        if (tid == 0) { while (ld_acq(&g_cnt[h]) != CNT_TARGET) __nanosleep(128); }
        __syncthreads();

        for (int i = tid; i < NS * NO; i += 512) {
            const int s = i >> 8, o = i & 255;
            s_z[i] = g_z[(size_t)(s * NH + h) * NO + o];
        }
        __syncthreads();

        // 4 GroupNorm+softmax, two 256-thread groups per pass
#pragma unroll
        for (int pass = 0; pass < 2; pass++) {
            const int grp = tid >> 8;
            const int s = pass * 2 + grp;
            const int o = tid & 255;
            const int wg = (tid >> 5) & 7;

            float v = s_z[s * NO + o];
            float su = warp_sum(v);
            float sq = warp_sum(v * v);
            if (lane == 0) { rsum[grp * 8 + wg] = su; rsq[grp * 8 + wg] = sq; }
            __syncthreads();
            float sum = 0.f, sqs = 0.f;
#pragma unroll
            for (int j = 0; j < 8; j++) { sum += rsum[grp * 8 + j]; sqs += rsq[grp * 8 + j]; }
            float mean = sum * (1.f / NO);
            float var  = sqs * (1.f / NO) - mean * mean;
            const int gidx = (s * NH + h) * NO + o;
            float zn = (v - mean) * rsqrtf(var + 1e-5f) * g2[gidx] + b2[gidx];

            float mx = zn;
#pragma unroll
            for (int m = 16; m; m >>= 1) mx = fmaxf(mx, __shfl_xor_sync(0xffffffffu, mx, m));
            if (lane == 0) rmax[grp * 8 + wg] = mx;
            __syncthreads();
            float M = -INFINITY;
#pragma unroll
            for (int j = 0; j < 8; j++) M = fmaxf(M, rmax[grp * 8 + j]);

            float e = expf(zn - M);
            float se = warp_sum(e);
            if (lane == 0) resum[grp * 8 + wg] = se;
            __syncthreads();
            float es = 0.f;
#pragma unroll
            for (int j = 0; j < 8; j++) es += resum[grp * 8 + j];
            s_z[s * NO + o] = e / es;
            __syncthreads();
        }

        const int o = tid;
        float osm = 0.f, part = 0.f;
        if (tid < NO) {
            osm = s_z[o] + s_z[NO + o] + s_z[2 * NO + o] + s_z[3 * NO + o];
            part = woo[h * 2 * NO + o] * s_lp[o] + woo[h * 2 * NO + NO + o] * osm;
        }
        float ps = warp_sum(part);
        if (lane == 0) redg[warp] = ps;
        __syncthreads();
        float gl = 0.f;
#pragma unroll
        for (int j = 0; j < 16; j++) gl += redg[j];
        float onoff = 1.f / (1.f + expf(-gl));

        if (tid < NO) {
            float oo = onoff * osm;
            float out0 = fmaxf(oo, 1e-14f);
            float sc = g_scalar[h * NO + o];
            float raw = oo * sc;
            float out1 = (fabsf(raw) <= 1e-14f) ? 1e-14f : raw;
            out[o * NH + h] = out0;
            out[NO * NH + o * NH + h] = out1;
        }
        __syncthreads();
        if (tid == 0) { g_cnt[h] = 0u; g_cntb[h] = 0u; }
    }
}

// ---------------------------------------------------------------------------
extern "C" void kernel_launch(void* const* d_in, const int* in_sizes, int n_in,
                              void* d_out, int out_size)
{
    const float* x    = (const float*)d_in[0];
    const float* last = (const float*)d_in[1];
    const float* qw   = (const float*)d_in[2];
    const float* w1   = (const float*)d_in[3];
    const float* g1   = (const float*)d_in[4];
    const float* b1   = (const float*)d_in[5];
    const float* w2   = (const float*)d_in[6];
    const float* g2   = (const float*)d_in[7];
    const float* b2   = (const float*)d_in[8];
    const float* ws   = (const float*)d_in[9];
    const float* woo  = (const float*)d_in[10];
    float* out = (float*)d_out;

    k_main<<<NBLK, 512>>>(x, qw, w1, g1, b1, w2, g2, b2, ws, last, woo, out);
}